// round 6
// baseline (speedup 1.0000x reference)
#include <cuda_runtime.h>
#include <math.h>

#define N_NODES   100000
#define N_EDGES   1600000
#define D         128
#define N_GRAPHS  128
#define N_CLASSES 10

// ---------------- scratch (static device globals; no allocs) ----------------
__device__ __align__(16) float g_h  [(size_t)N_NODES * D];   // ping buffer
__device__ __align__(16) float g_buf[(size_t)N_NODES * D];   // pong buffer
__device__ __align__(16) float g_agg[(size_t)N_NODES * D];   // aggregation acc
__device__ float g_dinv[N_NODES];
__device__ float g_deg [N_NODES];
__device__ __align__(16) float g_sums[N_GRAPHS * D];
__device__ float g_counts[N_GRAPHS];

// ---------------- setup kernels ----------------
__global__ void zero_kernel() {
    int i = blockIdx.x * blockDim.x + threadIdx.x;
    if (i < N_NODES)      g_deg[i]    = 0.0f;
    if (i < N_GRAPHS * D) g_sums[i]   = 0.0f;
    if (i < N_GRAPHS)     g_counts[i] = 0.0f;
}

__global__ void deg_kernel(const int* __restrict__ dst) {
    int e = blockIdx.x * blockDim.x + threadIdx.x;
    if (e < N_EDGES) atomicAdd(&g_deg[dst[e]], 1.0f);
}

__global__ void dinv_kernel() {
    int i = blockIdx.x * blockDim.x + threadIdx.x;
    if (i < N_NODES) g_dinv[i] = rsqrtf(g_deg[i] + 1.0f);
}

__global__ void counts_kernel(const int* __restrict__ batch) {
    int i = blockIdx.x * blockDim.x + threadIdx.x;
    if (i < N_NODES) atomicAdd(&g_counts[batch[i]], 1.0f);
}

// ---------------- GEMM: H[n,128] = X[n,128] @ W[128,128] ----------------
// 256 threads/block, 32 rows/block. Thread (lane = t%32, rt = t/32):
// cols 4*lane..4*lane+3, rows rt + 8*j (j=0..3). 16 accumulators.
__global__ void gemm_kernel(const float* __restrict__ X,
                            const float* __restrict__ W,
                            float* __restrict__ H) {
    int block_row = blockIdx.x * 32;
    int lane = threadIdx.x & 31;
    int rt   = threadIdx.x >> 5;

    float acc[4][4];
#pragma unroll
    for (int j = 0; j < 4; j++)
#pragma unroll
        for (int c = 0; c < 4; c++) acc[j][c] = 0.0f;

    for (int k = 0; k < D; k += 4) {
        float4 wv[4];
#pragma unroll
        for (int kk = 0; kk < 4; kk++)
            wv[kk] = *(const float4*)&W[(k + kk) * D + lane * 4];
#pragma unroll
        for (int j = 0; j < 4; j++) {
            int r = block_row + rt + 8 * j;
            float4 xv = *(const float4*)&X[(size_t)r * D + k];
            acc[j][0] += xv.x * wv[0].x; acc[j][1] += xv.x * wv[0].y;
            acc[j][2] += xv.x * wv[0].z; acc[j][3] += xv.x * wv[0].w;
            acc[j][0] += xv.y * wv[1].x; acc[j][1] += xv.y * wv[1].y;
            acc[j][2] += xv.y * wv[1].z; acc[j][3] += xv.y * wv[1].w;
            acc[j][0] += xv.z * wv[2].x; acc[j][1] += xv.z * wv[2].y;
            acc[j][2] += xv.z * wv[2].z; acc[j][3] += xv.z * wv[2].w;
            acc[j][0] += xv.w * wv[3].x; acc[j][1] += xv.w * wv[3].y;
            acc[j][2] += xv.w * wv[3].z; acc[j][3] += xv.w * wv[3].w;
        }
    }
#pragma unroll
    for (int j = 0; j < 4; j++) {
        int r = block_row + rt + 8 * j;
        float4 o = make_float4(acc[j][0], acc[j][1], acc[j][2], acc[j][3]);
        *(float4*)&H[(size_t)r * D + lane * 4] = o;
    }
}

// ---------------- agg = dinv_i^2 * h_i (self-loop term, full overwrite) ----
__global__ void init_kernel(const float* __restrict__ h, float* __restrict__ agg) {
    int idx = blockIdx.x * blockDim.x + threadIdx.x;   // over N*32 float4s
    if (idx >= N_NODES * 32) return;
    int node = idx >> 5;
    float di = g_dinv[node];
    float s = di * di;
    float4 v = ((const float4*)h)[idx];
    ((float4*)agg)[idx] = make_float4(v.x * s, v.y * s, v.z * s, v.w * s);
}

// ---------------- edge scatter: warp per edge, lane per float4 -------------
// 4 scalar atomicAdd (no return -> REDG.ADD.F32) per lane.
__global__ void scatter_kernel(const int* __restrict__ ei,
                               const float* __restrict__ h,
                               float* __restrict__ agg) {
    int warp = (blockIdx.x * blockDim.x + threadIdx.x) >> 5;
    if (warp >= N_EDGES) return;
    int lane = threadIdx.x & 31;
    int s = ei[warp];              // src (broadcast load)
    int d = ei[N_EDGES + warp];    // dst
    float norm = g_dinv[s] * g_dinv[d];
    float4 v = ((const float4*)(h + (size_t)s * D))[lane];
    float* p = agg + (size_t)d * D + lane * 4;
    atomicAdd(p + 0, v.x * norm);
    atomicAdd(p + 1, v.y * norm);
    atomicAdd(p + 2, v.z * norm);
    atomicAdd(p + 3, v.w * norm);
}

// ---------------- out = [relu](agg + b) ----------------
__global__ void finalize_kernel(const float* __restrict__ agg,
                                const float* __restrict__ b,
                                float* __restrict__ out, int relu) {
    int idx = blockIdx.x * blockDim.x + threadIdx.x;
    if (idx >= N_NODES * 32) return;
    float4 bb = ((const float4*)b)[idx & 31];
    float4 v = ((const float4*)agg)[idx];
    v.x += bb.x; v.y += bb.y; v.z += bb.z; v.w += bb.w;
    if (relu) {
        v.x = fmaxf(v.x, 0.0f); v.y = fmaxf(v.y, 0.0f);
        v.z = fmaxf(v.z, 0.0f); v.w = fmaxf(v.w, 0.0f);
    }
    ((float4*)out)[idx] = v;
}

// ---------------- final layer: (agg + b) pooled straight into g_sums ------
__global__ void finalize_pool_kernel(const float* __restrict__ agg,
                                     const float* __restrict__ b,
                                     const int* __restrict__ batch) {
    int idx = blockIdx.x * blockDim.x + threadIdx.x;
    if (idx >= N_NODES * 32) return;
    int node = idx >> 5;
    float4 bb = ((const float4*)b)[idx & 31];
    float4 v = ((const float4*)agg)[idx];
    v.x += bb.x; v.y += bb.y; v.z += bb.z; v.w += bb.w;
    int g = batch[node];
    float* p = &g_sums[g * D + (idx & 31) * 4];
    atomicAdd(p + 0, v.x);
    atomicAdd(p + 1, v.y);
    atomicAdd(p + 2, v.z);
    atomicAdd(p + 3, v.w);
}

// ---------------- head: mean-pool -> linear -> softmax --------------------
__global__ void head_kernel(const float* __restrict__ lin_W,
                            const float* __restrict__ lin_b,
                            float* __restrict__ out) {
    int g = threadIdx.x;
    if (g >= N_GRAPHS) return;
    float inv = 1.0f / fmaxf(g_counts[g], 1.0f);
    float logits[N_CLASSES];
#pragma unroll
    for (int j = 0; j < N_CLASSES; j++) logits[j] = lin_b[j];
    for (int c = 0; c < D; c++) {
        float p = g_sums[g * D + c] * inv;
#pragma unroll
        for (int j = 0; j < N_CLASSES; j++)
            logits[j] += p * lin_W[c * N_CLASSES + j];
    }
    float m = logits[0];
#pragma unroll
    for (int j = 1; j < N_CLASSES; j++) m = fmaxf(m, logits[j]);
    float ssum = 0.0f;
#pragma unroll
    for (int j = 0; j < N_CLASSES; j++) {
        logits[j] = expf(logits[j] - m);
        ssum += logits[j];
    }
    float isum = 1.0f / ssum;
#pragma unroll
    for (int j = 0; j < N_CLASSES; j++)
        out[g * N_CLASSES + j] = logits[j] * isum;
}

// ---------------- launch ----------------
extern "C" void kernel_launch(void* const* d_in, const int* in_sizes, int n_in,
                              void* d_out, int out_size) {
    const float* x     = (const float*)d_in[0];
    const int*   ei    = (const int*)d_in[1];    // int32! (JAX x64 disabled)
    const int*   batch = (const int*)d_in[2];    // int32!
    const float* W0    = (const float*)d_in[3];
    const float* b0    = (const float*)d_in[4];
    const float* W1    = (const float*)d_in[5];
    const float* b1    = (const float*)d_in[6];
    const float* W2    = (const float*)d_in[7];
    const float* b2    = (const float*)d_in[8];
    const float* lW    = (const float*)d_in[9];
    const float* lb    = (const float*)d_in[10];
    float* out = (float*)d_out;

    void *ph, *pb, *pa;
    cudaGetSymbolAddress(&ph, g_h);
    cudaGetSymbolAddress(&pb, g_buf);
    cudaGetSymbolAddress(&pa, g_agg);
    float* H = (float*)ph;
    float* B = (float*)pb;
    float* A = (float*)pa;

    const int NT = 256;
    const int node_blocks = (N_NODES + NT - 1) / NT;
    const int edge_blocks = (N_EDGES + NT - 1) / NT;
    const int gemm_blocks = N_NODES / 32;                  // 3125 (exact)
    const int elem_blocks = (N_NODES * 32 + NT - 1) / NT;  // elementwise float4
    const int scat_blocks = (N_EDGES / 8);                 // warp/edge, 8 warps/blk

    zero_kernel<<<node_blocks, NT>>>();
    deg_kernel<<<edge_blocks, NT>>>(ei + N_EDGES);
    dinv_kernel<<<node_blocks, NT>>>();
    counts_kernel<<<node_blocks, NT>>>(batch);

    // layer 0: in = x -> H
    gemm_kernel<<<gemm_blocks, NT>>>(x, W0, H);
    init_kernel<<<elem_blocks, NT>>>(H, A);
    scatter_kernel<<<scat_blocks, NT>>>(ei, H, A);
    finalize_kernel<<<elem_blocks, NT>>>(A, b0, H, 1);

    // layer 1: in = H -> B
    gemm_kernel<<<gemm_blocks, NT>>>(H, W1, B);
    init_kernel<<<elem_blocks, NT>>>(B, A);
    scatter_kernel<<<scat_blocks, NT>>>(ei, B, A);
    finalize_kernel<<<elem_blocks, NT>>>(A, b1, B, 1);

    // layer 2: in = B -> pooled sums directly
    gemm_kernel<<<gemm_blocks, NT>>>(B, W2, H);
    init_kernel<<<elem_blocks, NT>>>(H, A);
    scatter_kernel<<<scat_blocks, NT>>>(ei, H, A);
    finalize_pool_kernel<<<elem_blocks, NT>>>(A, b2, batch);

    head_kernel<<<1, 128>>>(lW, lb, out);
}

// round 8
// speedup vs baseline: 2.0413x; 2.0413x over previous
#include <cuda_runtime.h>
#include <math.h>

#define N_NODES   100000
#define N_EDGES   1600000
#define D         128
#define N_GRAPHS  128
#define N_CLASSES 10

// ---------------- scratch (static device globals; no allocs) ----------------
__device__ __align__(16) float g_h  [(size_t)N_NODES * D];   // ping buffer
__device__ __align__(16) float g_buf[(size_t)N_NODES * D];   // pong buffer
__device__ float g_dinv[N_NODES];
__device__ int   g_degi[N_NODES];
__device__ int   g_off [N_NODES + 1];
__device__ int   g_cur [N_NODES];
__device__ __align__(8) int2 g_csr[N_EDGES];                 // {src, norm bits}
__device__ __align__(16) float g_sums[N_GRAPHS * D];
__device__ int   g_end [N_GRAPHS];                           // cumulative node count

// ---------------- setup ----------------
__global__ void zero_kernel() {
    int i = blockIdx.x * blockDim.x + threadIdx.x;
    if (i < N_NODES)      g_degi[i] = 0;
    if (i < N_GRAPHS * D) g_sums[i] = 0.0f;
}

__global__ void hist_kernel(const int* __restrict__ dst) {
    int e = blockIdx.x * blockDim.x + threadIdx.x;
    if (e < N_EDGES) atomicAdd(&g_degi[dst[e]], 1);
}

__global__ void dinv_kernel() {
    int i = blockIdx.x * blockDim.x + threadIdx.x;
    if (i < N_NODES) g_dinv[i] = rsqrtf((float)g_degi[i] + 1.0f);
}

// single-block scan: 1024 threads, 98 nodes per thread
__global__ void scan_kernel() {
    __shared__ int sh[1024];
    const int CH = 98;
    int t = threadIdx.x;
    int base = t * CH;
    int lsum = 0;
    for (int k = 0; k < CH; k++) {
        int i = base + k;
        if (i < N_NODES) lsum += g_degi[i];
    }
    sh[t] = lsum;
    __syncthreads();
    for (int ofs = 1; ofs < 1024; ofs <<= 1) {
        int v = (t >= ofs) ? sh[t - ofs] : 0;
        __syncthreads();
        sh[t] += v;
        __syncthreads();
    }
    int run = (t > 0) ? sh[t - 1] : 0;
    for (int k = 0; k < CH; k++) {
        int i = base + k;
        if (i < N_NODES) {
            g_off[i] = run;
            g_cur[i] = run;
            run += g_degi[i];
        }
    }
    if (t == 1023) g_off[N_NODES] = sh[1023];
}

__global__ void place_kernel(const int* __restrict__ ei) {
    int e = blockIdx.x * blockDim.x + threadIdx.x;
    if (e >= N_EDGES) return;
    int s = ei[e];
    int d = ei[N_EDGES + e];
    int pos = atomicAdd(&g_cur[d], 1);
    float nrm = g_dinv[s] * g_dinv[d];
    g_csr[pos] = make_int2(s, __float_as_int(nrm));
}

// batch is sorted: record cumulative end index per graph (no atomics)
__global__ void boundary_kernel(const int* __restrict__ batch) {
    int i = blockIdx.x * blockDim.x + threadIdx.x;
    if (i >= N_NODES) return;
    int b  = batch[i];
    int bn = (i + 1 < N_NODES) ? batch[i + 1] : N_GRAPHS;
    for (int g = b; g < bn; g++) g_end[g] = i + 1;
    if (i == 0)
        for (int g = 0; g < b; g++) g_end[g] = 0;
}

// ---------------- GEMM: H[n,128] = X[n,128] @ W[128,128] ----------------
__global__ void gemm_kernel(const float* __restrict__ X,
                            const float* __restrict__ W,
                            float* __restrict__ H) {
    int block_row = blockIdx.x * 32;
    int lane = threadIdx.x & 31;
    int rt   = threadIdx.x >> 5;

    float acc[4][4];
#pragma unroll
    for (int j = 0; j < 4; j++)
#pragma unroll
        for (int c = 0; c < 4; c++) acc[j][c] = 0.0f;

    for (int k = 0; k < D; k += 4) {
        float4 wv[4];
#pragma unroll
        for (int kk = 0; kk < 4; kk++)
            wv[kk] = *(const float4*)&W[(k + kk) * D + lane * 4];
#pragma unroll
        for (int j = 0; j < 4; j++) {
            int r = block_row + rt + 8 * j;
            float4 xv = *(const float4*)&X[(size_t)r * D + k];
            acc[j][0] += xv.x * wv[0].x; acc[j][1] += xv.x * wv[0].y;
            acc[j][2] += xv.x * wv[0].z; acc[j][3] += xv.x * wv[0].w;
            acc[j][0] += xv.y * wv[1].x; acc[j][1] += xv.y * wv[1].y;
            acc[j][2] += xv.y * wv[1].z; acc[j][3] += xv.y * wv[1].w;
            acc[j][0] += xv.z * wv[2].x; acc[j][1] += xv.z * wv[2].y;
            acc[j][2] += xv.z * wv[2].z; acc[j][3] += xv.z * wv[2].w;
            acc[j][0] += xv.w * wv[3].x; acc[j][1] += xv.w * wv[3].y;
            acc[j][2] += xv.w * wv[3].z; acc[j][3] += xv.w * wv[3].w;
        }
    }
#pragma unroll
    for (int j = 0; j < 4; j++) {
        int r = block_row + rt + 8 * j;
        float4 o = make_float4(acc[j][0], acc[j][1], acc[j][2], acc[j][3]);
        *(float4*)&H[(size_t)r * D + lane * 4] = o;
    }
}

// ---------------- fused gather: out = [relu]( dinv^2*h + sum csr + b ) ----
__global__ void gather_kernel(const float* __restrict__ H,
                              const float* __restrict__ b,
                              float* __restrict__ out, int relu) {
    int node = (blockIdx.x * blockDim.x + threadIdx.x) >> 5;
    if (node >= N_NODES) return;
    int lane = threadIdx.x & 31;

    float di = g_dinv[node];
    float s  = di * di;
    float4 acc = ((const float4*)(H + (size_t)node * D))[lane];
    acc.x *= s; acc.y *= s; acc.z *= s; acc.w *= s;

    int beg = g_off[node], end = g_off[node + 1];
    for (int j = beg; j < end; j++) {
        int2 e = g_csr[j];                       // broadcast LDG.64
        float nrm = __int_as_float(e.y);
        float4 v = ((const float4*)(H + (size_t)e.x * D))[lane];
        acc.x += nrm * v.x; acc.y += nrm * v.y;
        acc.z += nrm * v.z; acc.w += nrm * v.w;
    }

    float4 bb = ((const float4*)b)[lane];
    acc.x += bb.x; acc.y += bb.y; acc.z += bb.z; acc.w += bb.w;
    if (relu) {
        acc.x = fmaxf(acc.x, 0.0f); acc.y = fmaxf(acc.y, 0.0f);
        acc.z = fmaxf(acc.z, 0.0f); acc.w = fmaxf(acc.w, 0.0f);
    }
    ((float4*)(out + (size_t)node * D))[lane] = acc;
}

// last layer: same gather, but pool straight into g_sums
__global__ void gather_pool_kernel(const float* __restrict__ H,
                                   const float* __restrict__ b,
                                   const int* __restrict__ batch) {
    int node = (blockIdx.x * blockDim.x + threadIdx.x) >> 5;
    if (node >= N_NODES) return;
    int lane = threadIdx.x & 31;

    float di = g_dinv[node];
    float s  = di * di;
    float4 acc = ((const float4*)(H + (size_t)node * D))[lane];
    acc.x *= s; acc.y *= s; acc.z *= s; acc.w *= s;

    int beg = g_off[node], end = g_off[node + 1];
    for (int j = beg; j < end; j++) {
        int2 e = g_csr[j];
        float nrm = __int_as_float(e.y);
        float4 v = ((const float4*)(H + (size_t)e.x * D))[lane];
        acc.x += nrm * v.x; acc.y += nrm * v.y;
        acc.z += nrm * v.z; acc.w += nrm * v.w;
    }

    float4 bb = ((const float4*)b)[lane];
    acc.x += bb.x; acc.y += bb.y; acc.z += bb.z; acc.w += bb.w;

    int g = batch[node];
    float* p = &g_sums[g * D + lane * 4];
    atomicAdd(p + 0, acc.x);
    atomicAdd(p + 1, acc.y);
    atomicAdd(p + 2, acc.z);
    atomicAdd(p + 3, acc.w);
}

// ---------------- head: mean-pool -> linear -> softmax --------------------
__global__ void head_kernel(const float* __restrict__ lin_W,
                            const float* __restrict__ lin_b,
                            float* __restrict__ out) {
    int g = threadIdx.x;
    if (g >= N_GRAPHS) return;
    int cnt = g_end[g] - (g > 0 ? g_end[g - 1] : 0);
    float inv = 1.0f / fmaxf((float)cnt, 1.0f);
    float logits[N_CLASSES];
#pragma unroll
    for (int j = 0; j < N_CLASSES; j++) logits[j] = lin_b[j];
    for (int c = 0; c < D; c++) {
        float p = g_sums[g * D + c] * inv;
#pragma unroll
        for (int j = 0; j < N_CLASSES; j++)
            logits[j] += p * lin_W[c * N_CLASSES + j];
    }
    float m = logits[0];
#pragma unroll
    for (int j = 1; j < N_CLASSES; j++) m = fmaxf(m, logits[j]);
    float ssum = 0.0f;
#pragma unroll
    for (int j = 0; j < N_CLASSES; j++) {
        logits[j] = expf(logits[j] - m);
        ssum += logits[j];
    }
    float isum = 1.0f / ssum;
#pragma unroll
    for (int j = 0; j < N_CLASSES; j++)
        out[g * N_CLASSES + j] = logits[j] * isum;
}

// ---------------- launch ----------------
extern "C" void kernel_launch(void* const* d_in, const int* in_sizes, int n_in,
                              void* d_out, int out_size) {
    const float* x     = (const float*)d_in[0];
    const int*   ei    = (const int*)d_in[1];    // int32 (JAX x64 disabled)
    const int*   batch = (const int*)d_in[2];
    const float* W0    = (const float*)d_in[3];
    const float* b0    = (const float*)d_in[4];
    const float* W1    = (const float*)d_in[5];
    const float* b1    = (const float*)d_in[6];
    const float* W2    = (const float*)d_in[7];
    const float* b2    = (const float*)d_in[8];
    const float* lW    = (const float*)d_in[9];
    const float* lb    = (const float*)d_in[10];
    float* out = (float*)d_out;

    void *ph, *pb;
    cudaGetSymbolAddress(&ph, g_h);
    cudaGetSymbolAddress(&pb, g_buf);
    float* H = (float*)ph;
    float* B = (float*)pb;

    const int NT = 256;
    const int node_blocks = (N_NODES + NT - 1) / NT;
    const int edge_blocks = (N_EDGES + NT - 1) / NT;
    const int gemm_blocks = N_NODES / 32;            // 3125
    const int gath_blocks = N_NODES / 8;             // warp/node, 8/block, exact

    // CSR build + graph bookkeeping (per call; graph-capturable, deterministic)
    zero_kernel<<<node_blocks, NT>>>();
    hist_kernel<<<edge_blocks, NT>>>(ei + N_EDGES);
    dinv_kernel<<<node_blocks, NT>>>();
    scan_kernel<<<1, 1024>>>();
    place_kernel<<<edge_blocks, NT>>>(ei);
    boundary_kernel<<<node_blocks, NT>>>(batch);

    // layer 0: x -> H -> B
    gemm_kernel<<<gemm_blocks, NT>>>(x, W0, H);
    gather_kernel<<<gath_blocks, NT>>>(H, b0, B, 1);

    // layer 1: B -> H -> B (reuse H as gemm output)
    gemm_kernel<<<gemm_blocks, NT>>>(B, W1, H);
    gather_kernel<<<gath_blocks, NT>>>(H, b1, B, 1);

    // layer 2: B -> H -> pooled sums
    gemm_kernel<<<gemm_blocks, NT>>>(B, W2, H);
    gather_pool_kernel<<<gath_blocks, NT>>>(H, b2, batch);

    head_kernel<<<1, 128>>>(lW, lb, out);
}